// round 6
// baseline (speedup 1.0000x reference)
#include <cuda_runtime.h>
#include <cstddef>

#define NB 32
#define TT 2048
#define DD 512
#define HH 512
#define GG 2048   // 4*HH

// ---------------- device scratch ----------------
__device__ float g_P[(size_t)TT * GG * NB];   // [t][g][n]
__device__ float g_h[2 * HH * NB];            // double-buffered hidden, [k][n]
__device__ unsigned g_hflag[8][32];           // [group][block-in-group]; one 128B line per group

// ---------------- helpers ----------------
__device__ __forceinline__ unsigned long long pk2(float lo, float hi) {
    unsigned long long r;
    asm("mov.b64 %0, {%1, %2};" : "=l"(r) : "f"(lo), "f"(hi));
    return r;
}
__device__ __forceinline__ void up2(unsigned long long v, float &lo, float &hi) {
    asm("mov.b64 {%0, %1}, %2;" : "=f"(lo), "=f"(hi) : "l"(v));
}
__device__ __forceinline__ void fma2(unsigned long long &d, unsigned long long a,
                                     unsigned long long b) {
    asm("fma.rn.f32x2 %0, %1, %2, %0;" : "+l"(d) : "l"(a), "l"(b));
}
__device__ __forceinline__ unsigned ld_acq(const unsigned* p) {
    unsigned v;
    asm volatile("ld.acquire.gpu.u32 %0, [%1];" : "=r"(v) : "l"(p) : "memory");
    return v;
}
__device__ __forceinline__ void st_rel(unsigned* p, unsigned v) {
    asm volatile("st.release.gpu.u32 [%0], %1;" :: "l"(p), "r"(v) : "memory");
}
__device__ __forceinline__ void fence_gpu() {
    asm volatile("fence.acq_rel.gpu;" ::: "memory");
}
__device__ __forceinline__ float fsig(float v) {
    float e = __expf(-v);
    return __fdividef(1.f, 1.f + e);
}
__device__ __forceinline__ float ftanh(float v) {
    float a = fabsf(v);
    float e = __expf(-2.f * a);
    float r = __fdividef(1.f - e, 1.f + e);
    return copysignf(r, v);
}

// ---------------- reset kernel ----------------
__global__ void reset_kernel() {
    int idx = blockIdx.x * blockDim.x + threadIdx.x;
    int n = gridDim.x * blockDim.x;
    for (int i = idx; i < 2 * HH * NB; i += n) g_h[i] = 0.f;
    for (int i = idx; i < 8 * 32; i += n) (&g_hflag[0][0])[i] = 0u;
}

// ---------------- Phase 1: P[t][g][n] = x @ W_ih^T + (b_ih + b_hh) ----------------
// Tile: 128 g-rows x 64 cols (2 timesteps x 32 batch), BK=16, 256 threads,
// microtile 8g x 4c per thread, f32x2 paired along g. At the fma-pipe floor.
__global__ __launch_bounds__(256) void phase1_kernel(const float* __restrict__ x,
                                                     const float* __restrict__ Wih,
                                                     const float* __restrict__ bih,
                                                     const float* __restrict__ bhh) {
    __shared__ float Ws[16][132];
    __shared__ float Xs[16][68];

    const int tid = threadIdx.x;
    const int ct  = blockIdx.x;       // 0..1023 (2 timesteps each)
    const int gt  = blockIdx.y;       // 0..15
    const int g0  = gt * 128;
    const int t0  = ct * 2;
    const int tx  = tid & 15;
    const int ty  = tid >> 4;
    const int gq  = tid >> 2;
    const int kq  = tid & 3;

    unsigned long long acc[4][4];
    #pragma unroll
    for (int p = 0; p < 4; ++p)
        #pragma unroll
        for (int j = 0; j < 4; ++j) acc[p][j] = 0ULL;

    const int cc = gq;
    const int lt = cc >> 5, nn = cc & 31;
    const float* xrow = x + ((size_t)nn * TT + (size_t)(t0 + lt)) * DD;

    for (int kt = 0; kt < 32; ++kt) {
        const int k0 = kt * 16;
        #pragma unroll
        for (int h = 0; h < 2; ++h) {
            int gcol = h * 64 + gq;
            float4 wv = *(const float4*)(Wih + (size_t)(g0 + gcol) * DD + k0 + kq * 4);
            Ws[kq * 4 + 0][gcol] = wv.x;
            Ws[kq * 4 + 1][gcol] = wv.y;
            Ws[kq * 4 + 2][gcol] = wv.z;
            Ws[kq * 4 + 3][gcol] = wv.w;
        }
        {
            float4 xv = *(const float4*)(xrow + k0 + kq * 4);
            Xs[kq * 4 + 0][cc] = xv.x;
            Xs[kq * 4 + 1][cc] = xv.y;
            Xs[kq * 4 + 2][cc] = xv.z;
            Xs[kq * 4 + 3][cc] = xv.w;
        }
        __syncthreads();
        #pragma unroll
        for (int k = 0; k < 16; ++k) {
            ulonglong2 wA = *(const ulonglong2*)&Ws[k][ty * 8];
            ulonglong2 wB = *(const ulonglong2*)&Ws[k][ty * 8 + 4];
            float4 xv = *(const float4*)&Xs[k][tx * 4];
            unsigned long long b0 = pk2(xv.x, xv.x);
            unsigned long long b1 = pk2(xv.y, xv.y);
            unsigned long long b2 = pk2(xv.z, xv.z);
            unsigned long long b3 = pk2(xv.w, xv.w);
            fma2(acc[0][0], wA.x, b0); fma2(acc[0][1], wA.x, b1);
            fma2(acc[0][2], wA.x, b2); fma2(acc[0][3], wA.x, b3);
            fma2(acc[1][0], wA.y, b0); fma2(acc[1][1], wA.y, b1);
            fma2(acc[1][2], wA.y, b2); fma2(acc[1][3], wA.y, b3);
            fma2(acc[2][0], wB.x, b0); fma2(acc[2][1], wB.x, b1);
            fma2(acc[2][2], wB.x, b2); fma2(acc[2][3], wB.x, b3);
            fma2(acc[3][0], wB.y, b0); fma2(acc[3][1], wB.y, b1);
            fma2(acc[3][2], wB.y, b2); fma2(acc[3][3], wB.y, b3);
        }
        __syncthreads();
    }

    const int c0 = tx * 4;
    const int ltS = c0 >> 5, nS = c0 & 31;
    const int tS = t0 + ltS;
    #pragma unroll
    for (int p = 0; p < 4; ++p) {
        int gA = g0 + ty * 8 + 2 * p;
        float bA = bih[gA] + bhh[gA];
        float bB = bih[gA + 1] + bhh[gA + 1];
        float lo0, hi0, lo1, hi1, lo2_, hi2_, lo3, hi3;
        up2(acc[p][0], lo0, hi0);
        up2(acc[p][1], lo1, hi1);
        up2(acc[p][2], lo2_, hi2_);
        up2(acc[p][3], lo3, hi3);
        float* dst = g_P + (size_t)tS * (GG * NB) + (size_t)gA * NB + nS;
        *(float4*)dst        = make_float4(lo0 + bA, lo1 + bA, lo2_ + bA, lo3 + bA);
        *(float4*)(dst + NB) = make_float4(hi0 + bB, hi1 + bB, hi2_ + bB, hi3 + bB);
    }
}

// ---------------- Phase 2: persistent scan, distributed flag barrier ----------------
// 128 blocks x 256 threads (1 per SM). Block b owns hidden units j0..j0+3
// (16 gate rows); W_hh slice in shared. Warp w covers k-chunk [64w,64w+64),
// produced by blocks 16w..16w+15 -> warp waits only on those 16 flags.
// c-state lives in registers of threads 0..127 for the whole kernel.
__global__ __launch_bounds__(256, 1) void lstm_seq_kernel(const float* __restrict__ Whh,
                                                          float* __restrict__ y) {
    __shared__ float Wsh[HH * 16];        // [k][gi]  32 KB
    __shared__ float part[8][16][NB];     // [warp][gi][n]  16 KB

    const int tid  = threadIdx.x;
    const int warp = tid >> 5;
    const int lane = tid & 31;
    const int b    = blockIdx.x;          // 0..127
    const int j0   = b * 4;

    for (int i = tid; i < 16 * HH; i += 256) {
        int k  = i & (HH - 1);
        int gi = i >> 9;
        int q  = gi >> 2, u2 = gi & 3;
        Wsh[k * 16 + gi] = Whh[(size_t)(q * HH + j0 + u2) * HH + k];
    }

    const int u  = warp;                  // gate-apply mapping for tid<128
    const int k0 = warp * 64;
    float c_state = 0.f;
    __syncthreads();

    #pragma unroll 1
    for (unsigned t = 0; t < TT; ++t) {
        const float* hin = g_h + (t & 1) * (HH * NB);
        float* hout      = g_h + ((t + 1) & 1) * (HH * NB);

        // prefetch P (independent of h) BEFORE the flag wait
        float pre0 = 0.f, pre1 = 0.f, pre2 = 0.f, pre3 = 0.f;
        if (tid < 128) {
            const float* Pt = g_P + (size_t)t * (GG * NB) + (size_t)(j0 + u) * NB + lane;
            pre0 = Pt[0 * HH * NB];
            pre1 = Pt[1 * HH * NB];
            pre2 = Pt[2 * HH * NB];
            pre3 = Pt[3 * HH * NB];
        }

        // wait: this warp's 16 producer blocks have published step t inputs
        {
            unsigned o;
            do {
                o = 1u;
                if (lane < 16) o = (ld_acq(&g_hflag[warp][lane]) >= t) ? 1u : 0u;
            } while (!__all_sync(0xffffffffu, o));
        }

        // load this warp's h chunk (L2: written by peer SMs last step)
        float hr[64];
        #pragma unroll
        for (int kk = 0; kk < 64; ++kk)
            hr[kk] = __ldcg(hin + (k0 + kk) * NB + lane);

        unsigned long long acc[8];
        #pragma unroll
        for (int p = 0; p < 8; ++p) acc[p] = 0ULL;

        #pragma unroll
        for (int kk = 0; kk < 64; ++kk) {
            unsigned long long hb = pk2(hr[kk], hr[kk]);
            const ulonglong2* wr = (const ulonglong2*)(Wsh + (size_t)(k0 + kk) * 16);
            ulonglong2 w03 = wr[0];
            ulonglong2 w47 = wr[1];
            ulonglong2 w8b = wr[2];
            ulonglong2 wcf = wr[3];
            fma2(acc[0], w03.x, hb); fma2(acc[1], w03.y, hb);
            fma2(acc[2], w47.x, hb); fma2(acc[3], w47.y, hb);
            fma2(acc[4], w8b.x, hb); fma2(acc[5], w8b.y, hb);
            fma2(acc[6], wcf.x, hb); fma2(acc[7], wcf.y, hb);
        }

        // single-stage partial publish
        #pragma unroll
        for (int p = 0; p < 8; ++p) {
            float lo, hi;
            up2(acc[p], lo, hi);
            part[warp][2 * p][lane]     = lo;
            part[warp][2 * p + 1][lane] = hi;
        }
        __syncthreads();

        // final reduce + gates (threads 0..127: one (hidden unit u, batch n) each)
        if (tid < 128) {
            float vi = pre0, vf = pre1, vo = pre2, vg = pre3;
            #pragma unroll
            for (int w2 = 0; w2 < 8; ++w2) {
                vi += part[w2][0 * 4 + u][lane];
                vf += part[w2][1 * 4 + u][lane];
                vo += part[w2][2 * 4 + u][lane];
                vg += part[w2][3 * 4 + u][lane];
            }
            float ig = fsig(vi);
            float fg = fsig(vf);
            float og = fsig(vo);
            float gt_ = ftanh(vg);
            c_state = fg * c_state + ig * gt_;
            float hn = og * ftanh(c_state);
            hout[(j0 + u) * NB + lane] = hn;
            y[(size_t)lane * (TT * HH) + (size_t)t * HH + (j0 + u)] = hn;
        }
        __syncthreads();   // hout stores done + part consumed before publish/reuse

        // publish step t+1 readiness of this block's 4 h rows
        if (tid == 0) {
            fence_gpu();   // make CTA's hout stores visible before the flag
            st_rel(&g_hflag[b >> 4][b & 15], t + 1);
        }
    }
}

// ---------------- launcher ----------------
extern "C" void kernel_launch(void* const* d_in, const int* in_sizes, int n_in,
                              void* d_out, int out_size) {
    const float* x   = (const float*)d_in[0];
    const float* Wih = (const float*)d_in[1];
    const float* bih = (const float*)d_in[2];
    const float* Whh = (const float*)d_in[3];
    const float* bhh = (const float*)d_in[4];
    float* y = (float*)d_out;

    reset_kernel<<<64, 256>>>();

    dim3 g1(1024, 16);
    phase1_kernel<<<g1, 256>>>(x, Wih, bih, bhh);

    lstm_seq_kernel<<<128, 256>>>(Whh, y);
}

// round 7
// speedup vs baseline: 1.3055x; 1.3055x over previous
#include <cuda_runtime.h>
#include <cstddef>

#define NB 32
#define TT 2048
#define DD 512
#define HH 512
#define GG 2048   // 4*HH

// ---------------- device scratch ----------------
__device__ float g_P[(size_t)TT * GG * NB];   // [t][g][n]
// per-stream double-buffered hidden: [s][buf][k][16]
__device__ float g_h2[2 * 2 * HH * 16];
// flags: [s][group][slot] ; each group row = 128B line; slot = producer block & 7
__device__ unsigned g_hflag2[2][16][32];

// ---------------- helpers ----------------
__device__ __forceinline__ unsigned long long pk2(float lo, float hi) {
    unsigned long long r;
    asm("mov.b64 %0, {%1, %2};" : "=l"(r) : "f"(lo), "f"(hi));
    return r;
}
__device__ __forceinline__ void up2(unsigned long long v, float &lo, float &hi) {
    asm("mov.b64 {%0, %1}, %2;" : "=f"(lo), "=f"(hi) : "l"(v));
}
__device__ __forceinline__ void fma2(unsigned long long &d, unsigned long long a,
                                     unsigned long long b) {
    asm("fma.rn.f32x2 %0, %1, %2, %0;" : "+l"(d) : "l"(a), "l"(b));
}
__device__ __forceinline__ unsigned ld_acq(const unsigned* p) {
    unsigned v;
    asm volatile("ld.acquire.gpu.u32 %0, [%1];" : "=r"(v) : "l"(p) : "memory");
    return v;
}
__device__ __forceinline__ void st_rel(unsigned* p, unsigned v) {
    asm volatile("st.release.gpu.u32 [%0], %1;" :: "l"(p), "r"(v) : "memory");
}
__device__ __forceinline__ void fence_gpu() {
    asm volatile("fence.acq_rel.gpu;" ::: "memory");
}
__device__ __forceinline__ float fsig(float v) {
    float e = __expf(-v);
    return __fdividef(1.f, 1.f + e);
}
__device__ __forceinline__ float ftanh(float v) {
    float a = fabsf(v);
    float e = __expf(-2.f * a);
    float r = __fdividef(1.f - e, 1.f + e);
    return copysignf(r, v);
}

// ---------------- reset kernel ----------------
__global__ void reset_kernel() {
    int idx = blockIdx.x * blockDim.x + threadIdx.x;
    int n = gridDim.x * blockDim.x;
    for (int i = idx; i < 2 * 2 * HH * 16; i += n) g_h2[i] = 0.f;
    for (int i = idx; i < 2 * 16 * 32; i += n) (&g_hflag2[0][0][0])[i] = 0u;
}

// ---------------- Phase 1 (unchanged, at fma-pipe floor) ----------------
__global__ __launch_bounds__(256) void phase1_kernel(const float* __restrict__ x,
                                                     const float* __restrict__ Wih,
                                                     const float* __restrict__ bih,
                                                     const float* __restrict__ bhh) {
    __shared__ float Ws[16][132];
    __shared__ float Xs[16][68];

    const int tid = threadIdx.x;
    const int ct  = blockIdx.x;
    const int gt  = blockIdx.y;
    const int g0  = gt * 128;
    const int t0  = ct * 2;
    const int tx  = tid & 15;
    const int ty  = tid >> 4;
    const int gq  = tid >> 2;
    const int kq  = tid & 3;

    unsigned long long acc[4][4];
    #pragma unroll
    for (int p = 0; p < 4; ++p)
        #pragma unroll
        for (int j = 0; j < 4; ++j) acc[p][j] = 0ULL;

    const int cc = gq;
    const int lt = cc >> 5, nn = cc & 31;
    const float* xrow = x + ((size_t)nn * TT + (size_t)(t0 + lt)) * DD;

    for (int kt = 0; kt < 32; ++kt) {
        const int k0 = kt * 16;
        #pragma unroll
        for (int h = 0; h < 2; ++h) {
            int gcol = h * 64 + gq;
            float4 wv = *(const float4*)(Wih + (size_t)(g0 + gcol) * DD + k0 + kq * 4);
            Ws[kq * 4 + 0][gcol] = wv.x;
            Ws[kq * 4 + 1][gcol] = wv.y;
            Ws[kq * 4 + 2][gcol] = wv.z;
            Ws[kq * 4 + 3][gcol] = wv.w;
        }
        {
            float4 xv = *(const float4*)(xrow + k0 + kq * 4);
            Xs[kq * 4 + 0][cc] = xv.x;
            Xs[kq * 4 + 1][cc] = xv.y;
            Xs[kq * 4 + 2][cc] = xv.z;
            Xs[kq * 4 + 3][cc] = xv.w;
        }
        __syncthreads();
        #pragma unroll
        for (int k = 0; k < 16; ++k) {
            ulonglong2 wA = *(const ulonglong2*)&Ws[k][ty * 8];
            ulonglong2 wB = *(const ulonglong2*)&Ws[k][ty * 8 + 4];
            float4 xv = *(const float4*)&Xs[k][tx * 4];
            unsigned long long b0 = pk2(xv.x, xv.x);
            unsigned long long b1 = pk2(xv.y, xv.y);
            unsigned long long b2 = pk2(xv.z, xv.z);
            unsigned long long b3 = pk2(xv.w, xv.w);
            fma2(acc[0][0], wA.x, b0); fma2(acc[0][1], wA.x, b1);
            fma2(acc[0][2], wA.x, b2); fma2(acc[0][3], wA.x, b3);
            fma2(acc[1][0], wA.y, b0); fma2(acc[1][1], wA.y, b1);
            fma2(acc[1][2], wA.y, b2); fma2(acc[1][3], wA.y, b3);
            fma2(acc[2][0], wB.x, b0); fma2(acc[2][1], wB.x, b1);
            fma2(acc[2][2], wB.x, b2); fma2(acc[2][3], wB.x, b3);
            fma2(acc[3][0], wB.y, b0); fma2(acc[3][1], wB.y, b1);
            fma2(acc[3][2], wB.y, b2); fma2(acc[3][3], wB.y, b3);
        }
        __syncthreads();
    }

    const int c0 = tx * 4;
    const int ltS = c0 >> 5, nS = c0 & 31;
    const int tS = t0 + ltS;
    #pragma unroll
    for (int p = 0; p < 4; ++p) {
        int gA = g0 + ty * 8 + 2 * p;
        float bA = bih[gA] + bhh[gA];
        float bB = bih[gA + 1] + bhh[gA + 1];
        float lo0, hi0, lo1, hi1, lo2_, hi2_, lo3, hi3;
        up2(acc[p][0], lo0, hi0);
        up2(acc[p][1], lo1, hi1);
        up2(acc[p][2], lo2_, hi2_);
        up2(acc[p][3], lo3, hi3);
        float* dst = g_P + (size_t)tS * (GG * NB) + (size_t)gA * NB + nS;
        *(float4*)dst        = make_float4(lo0 + bA, lo1 + bA, lo2_ + bA, lo3 + bA);
        *(float4*)(dst + NB) = make_float4(hi0 + bB, hi1 + bB, hi2_ + bB, hi3 + bB);
    }
}

// ---------------- Phase 2: stream-interleaved persistent scan ----------------
// 128 blocks x 512 threads (1/SM). Block b owns hidden units j0..j0+3
// (16 gate rows gi = q*4+u). Warp w (16 warps) covers k-chunk [32w,32w+32),
// produced by blocks 8w..8w+7 -> flag group w, slots 0..7.
// Two batch streams s=0 (n 0..15) / s=1 (n 16..31), alternated within each
// step: while stream s runs its FMA, the other stream's flag/h round-trip
// completes in the background, so flag checks are one-shot hits.
// Lane mapping in FMA: nl = lane&15 (batch col), ph = lane>>4 (gi half).
// c-state: threads of warps 0..3 hold c for (u=warp, s=lane>>4, n16=lane&15).
__global__ __launch_bounds__(512, 1) void lstm_seq_kernel(const float* __restrict__ Whh,
                                                          float* __restrict__ y) {
    __shared__ float Wsh[HH * 16];        // [k][gi]  32 KB
    __shared__ float part[16][16][16];    // [warp][gi][nl]  16 KB  (total 48 KB)

    const int tid  = threadIdx.x;
    const int warp = tid >> 5;
    const int lane = tid & 31;
    const int nl   = lane & 15;
    const int ph   = lane >> 4;
    const int b    = blockIdx.x;          // 0..127
    const int j0   = b * 4;
    const int k0   = warp * 32;

    for (int i = tid; i < 16 * HH; i += 512) {
        int k  = i & (HH - 1);
        int gi = i >> 9;
        int q  = gi >> 2, u2 = gi & 3;
        Wsh[k * 16 + gi] = Whh[(size_t)(q * HH + j0 + u2) * HH + k];
    }

    // gate-thread identity (warps 0-3): unit u, stream sg, batch col n16
    const int u   = warp;
    const int sg  = ph;          // this thread's gate stream (fixed by lane)
    const int n16 = nl;
    const bool is_gate = (warp < 4);
    float c_state = 0.f;
    __syncthreads();

    #pragma unroll 1
    for (unsigned t = 0; t < TT; ++t) {
        #pragma unroll
        for (int s = 0; s < 2; ++s) {
            // ---- gate threads of this stream: early P prefetch (indep of h) ----
            float pre0 = 0.f, pre1 = 0.f, pre2 = 0.f, pre3 = 0.f;
            const bool gact = is_gate && (sg == s);
            if (gact) {
                const float* Pt = g_P + (size_t)t * (GG * NB) + (size_t)(j0 + u) * NB
                                + 16 * s + n16;
                pre0 = Pt[0 * HH * NB];
                pre1 = Pt[1 * HH * NB];
                pre2 = Pt[2 * HH * NB];
                pre3 = Pt[3 * HH * NB];
            }

            // ---- one-shot flag check (usually hits due to stream slack) ----
            {
                unsigned o = 1u;
                if (lane < 8) o = (ld_acq(&g_hflag2[s][warp][lane]) >= t) ? 1u : 0u;
                while (!__all_sync(0xffffffffu, o)) {
                    __nanosleep(100);
                    if (lane < 8) o = (ld_acq(&g_hflag2[s][warp][lane]) >= t) ? 1u : 0u;
                }
            }

            // ---- load h chunk, packed ----
            const float* hin = g_h2 + ((size_t)(s * 2 + (t & 1)) * HH) * 16;
            unsigned long long hbr[32];
            #pragma unroll
            for (int kk = 0; kk < 32; ++kk) {
                float hv = __ldcg(hin + (k0 + kk) * 16 + nl);
                hbr[kk] = pk2(hv, hv);
            }

            // ---- FMA: 4 gi-pairs (half ph) x 16 n ----
            unsigned long long acc0 = 0ULL, acc1 = 0ULL, acc2 = 0ULL, acc3 = 0ULL;
            #pragma unroll
            for (int kk = 0; kk < 32; ++kk) {
                const ulonglong2* wr =
                    (const ulonglong2*)(Wsh + (size_t)(k0 + kk) * 16 + ph * 8);
                ulonglong2 w01 = wr[0];   // gi ph*8+0..3
                ulonglong2 w23 = wr[1];   // gi ph*8+4..7
                fma2(acc0, w01.x, hbr[kk]);
                fma2(acc1, w01.y, hbr[kk]);
                fma2(acc2, w23.x, hbr[kk]);
                fma2(acc3, w23.y, hbr[kk]);
            }

            // ---- publish partials ----
            {
                float lo, hi;
                up2(acc0, lo, hi); part[warp][ph * 8 + 0][nl] = lo; part[warp][ph * 8 + 1][nl] = hi;
                up2(acc1, lo, hi); part[warp][ph * 8 + 2][nl] = lo; part[warp][ph * 8 + 3][nl] = hi;
                up2(acc2, lo, hi); part[warp][ph * 8 + 4][nl] = lo; part[warp][ph * 8 + 5][nl] = hi;
                up2(acc3, lo, hi); part[warp][ph * 8 + 6][nl] = lo; part[warp][ph * 8 + 7][nl] = hi;
            }
            __syncthreads();   // (A) partials ready

            // ---- gates (64 threads) ----
            float hn = 0.f;
            if (gact) {
                float vi = pre0, vf = pre1, vo = pre2, vg = pre3;
                #pragma unroll
                for (int w2 = 0; w2 < 16; ++w2) {
                    vi += part[w2][0 * 4 + u][n16];
                    vf += part[w2][1 * 4 + u][n16];
                    vo += part[w2][2 * 4 + u][n16];
                    vg += part[w2][3 * 4 + u][n16];
                }
                float ig = fsig(vi);
                float fg = fsig(vf);
                float og = fsig(vo);
                float gt_ = ftanh(vg);
                c_state = fg * c_state + ig * gt_;
                hn = og * ftanh(c_state);
                // h store (coalesced 64B per warp)
                float* hout = g_h2 + ((size_t)(s * 2 + ((t + 1) & 1)) * HH) * 16;
                hout[(j0 + u) * 16 + n16] = hn;
            }
            __syncthreads();   // (B) h stores done + part consumed

            // ---- publish readiness (parallel release store; no atomics) ----
            if (tid == 16 * s) {
                fence_gpu();   // order CTA's h stores (pre-barrier) before flag
                st_rel(&g_hflag2[s][b >> 3][b & 7], t + 1);
            }

            // ---- y store AFTER publish: off the critical path / fence shadow ----
            if (gact) {
                y[(size_t)(16 * s + n16) * (TT * HH) + (size_t)t * HH + (j0 + u)] = hn;
            }
        }
    }
}

// ---------------- launcher ----------------
extern "C" void kernel_launch(void* const* d_in, const int* in_sizes, int n_in,
                              void* d_out, int out_size) {
    const float* x   = (const float*)d_in[0];
    const float* Wih = (const float*)d_in[1];
    const float* bih = (const float*)d_in[2];
    const float* Whh = (const float*)d_in[3];
    const float* bhh = (const float*)d_in[4];
    float* y = (float*)d_out;

    reset_kernel<<<64, 256>>>();

    dim3 g1(1024, 16);
    phase1_kernel<<<g1, 256>>>(x, Wih, bih, bhh);

    lstm_seq_kernel<<<128, 512>>>(Whh, y);
}